// round 10
// baseline (speedup 1.0000x reference)
#include <cuda_runtime.h>

#define INN   40
#define HID   16384
#define OUTN  22
#define FAN0  8192
#define FAN1  11
#define THRESH 0.3f
#define NBLK  64
#define NTHR  256
#define NWARP (NTHR / 32)
#define NTOT  (NBLK * NTHR)             // 16384 threads == HID
#define ROWF  (NTHR * FAN1)             // floats in a block's w1 slice (2816)
#define V4N   (ROWF / 4)                // 704 float4 per array per block
#define DECAY 0.95122942450071400910f   // float32(exp(-1/20))

// Scratch — __device__ globals (allocation-free rule). g_add_h / g_add_o are
// zero at load and restored to zero every execution (zero-on-consume). g_bar is
// MONOTONIC (never reset): replay r uses window [2r*NBLK, 2(r+1)*NBLK); g_gen
// is the gate/replay counter on its OWN 128B line (spinner polls must not
// contend with arrival atomics at the LTS — R8 regression proved this).
__device__ float g_add_h[HID];
__device__ float g_add_o[OUTN];
__device__ __align__(128) unsigned g_bar[32];   // [0]: monotonic arrival counter
__device__ __align__(128) unsigned g_gen[32];   // [0]: gate word / replay index

__global__ __launch_bounds__(NTHR, 1)
void snn_fused(const float* __restrict__ spikes,
               const float* __restrict__ w0,
               const int*   __restrict__ tgt0,
               const float* __restrict__ w1,
               const int*   __restrict__ tgt1,
               const int*   __restrict__ mt_p,
               float*       __restrict__ out)
{
    __shared__ float s_spk[INN];          // 2 * input_spikes
    __shared__ float s_bins[NWARP][24];   // warp-private output bins (22 used)
    __shared__ float s_w1[ROWF];          // staged w1 slice (vec4-loaded)
    __shared__ int   s_t1[ROWF];          // staged tgt1 slice

    const int tid = threadIdx.x;
    const int gid = blockIdx.x * NTHR + tid;   // one hidden neuron per thread
    const int wrp = tid >> 5;
    const int lan = tid & 31;

    // ── Stage spikes (broadcast line) + zero bins
    if (tid < INN) s_spk[tid] = 2.0f * spikes[tid];
    if (lan < 24) s_bins[wrp][lan] = 0.0f;

    // ── Vectorized speculative prefetch of phase-B operands (critical path —
    // issued first). Thread owns float4 chunks at vec index gid + 16384*k
    // (k=0..4); chunk k lies in input row i0 + 8k, i0 = gid>>11 (warp-uniform).
    const float4* w0v = (const float4*)w0;
    const int4*   t0v = (const int4*)tgt0;
    float4 wv[5];
    int4   tv[5];
#pragma unroll
    for (int k = 0; k < 5; ++k) {
        wv[k] = __ldg(w0v + (gid + NTOT * k));
        tv[k] = __ldg(t0v + (gid + NTOT * k));
    }

    // ── Cooperative vec4 staging of this block's w1/tgt1 slice (contiguous
    // 2816 floats each). ~176 line-touches instead of ~1936 scalar ones; this
    // was the dominant front-end L1tex wavefront drain. Consumed after bar1.
    float4 swv[3];
    int4   stv[3];
    {
        const float4* wsrc = (const float4*)w1   + blockIdx.x * V4N;
        const int4*   tsrc = (const int4*)tgt1   + blockIdx.x * V4N;
#pragma unroll
        for (int i = 0; i < 3; ++i) {
            const int idx = tid + i * NTHR;
            if (idx < V4N) { swv[i] = __ldg(wsrc + idx); stv[i] = __ldg(tsrc + idx); }
        }
    }
    const int mt = __ldg(mt_p);
    const unsigned gen = *(volatile unsigned*)&g_gen[0];   // replay index

    // fac_long = decay^(mt-1) (hidden under phase B; finisher/repair only)
    float fac_long = 1.0f;
    for (int k = 1; k < mt; ++k) fac_long *= DECAY;

    __syncthreads();   // s_spk + bins visible

    // ── Phase B: input -> hidden scatter (t=0). Per chunk: one warp-uniform
    // spike lookup, 4 predicated REDs with operands already in registers.
    const int i0 = gid >> 11;
#pragma unroll
    for (int k = 0; k < 5; ++k) {
        const float s = s_spk[i0 + 8 * k];
        if (s != 0.0f) {
            atomicAdd(&g_add_h[tv[k].x], s * wv[k].x);
            atomicAdd(&g_add_h[tv[k].y], s * wv[k].y);
            atomicAdd(&g_add_h[tv[k].z], s * wv[k].z);
            atomicAdd(&g_add_h[tv[k].w], s * wv[k].w);
        }
    }

    // ── Park the staged slices in shared (STS.128). Stalls only on the staging
    // LDGs; visibility to phase C is covered by bar1's __syncthreads.
    {
        float4* sw = (float4*)s_w1;
        int4*   st = (int4*)s_t1;
#pragma unroll
        for (int i = 0; i < 3; ++i) {
            const int idx = tid + i * NTHR;
            if (idx < V4N) { sw[idx] = swv[i]; st[idx] = stv[i]; }
        }
    }

    // ── Barrier 1: arrivals on g_bar, gate on g_gen (separate lines).
    __syncthreads();
    if (tid == 0) {
        __threadfence();                                       // release
        unsigned old = atomicAdd(&g_bar[0], 1u);
        if (old == (2u * gen + 1u) * NBLK - 1u) {
            *(volatile unsigned*)&g_gen[0] = gen + 1u;         // open gate
        } else {
            while (*(volatile unsigned*)&g_gen[0] == gen) { }
        }
        __threadfence();                                       // acquire
    }
    __syncthreads();

    // ── Phase C: hidden threshold (spikes possible only at t=0) + out scatter
    float a = g_add_h[gid] * DECAY;               // pot_h at end of t=0
    g_add_h[gid] = 0.0f;                          // zero-on-consume for replay
    const bool  sp  = (a >= THRESH);
    const float pot = sp ? 0.0f : a;

    // Speculative pot_h store: assume all_f=true => S=2 => fac=DECAY.
    out[2 * OUTN + gid] = (mt >= 1) ? pot * DECAY : 0.0f;

    if (sp) {
        const int base = tid * FAN1;              // 11·tid — conflict-free LDS
#pragma unroll
        for (int q = 0; q < FAN1; ++q)
            atomicAdd(&s_bins[wrp][s_t1[base + q]], s_w1[base + q]);
    }
    __syncthreads();
    if (wrp != 0) return;                          // warps 1..7 done

    // ── Warp 0: post output partials, arrive; only the LAST block finalizes.
    float v = 0.0f;
    if (lan < OUTN) {
#pragma unroll
        for (int w = 0; w < NWARP; ++w) v += s_bins[w][lan];
        if (v != 0.0f) atomicAdd(&g_add_o[lan], v);
    }
    __threadfence();                               // block's adds + pot_h stores
    unsigned old = 0;
    if (lan == 0) old = atomicAdd(&g_bar[0], 1u);
    const bool fin = __shfl_sync(0xffffffffu, old, 0) == (2u * gen + 2u) * NBLK - 1u;
    if (!fin) return;                              // 63 blocks exit here

    // ── Finisher (warp 0 of last-arriving block): totals -> outputs (+repair)
    __threadfence();                               // acquire: all adds/stores
    float ao = 0.0f;
    if (lan < OUTN) {
        ao = g_add_o[lan];
        g_add_o[lan] = 0.0f;                       // zero-on-consume for replay
    }
    const bool out_phase = (mt >= 2);              // outputs fire at t=1 or never
    const bool f    = (lan < OUTN) && out_phase && (ao * DECAY >= THRESH);
    const unsigned m = __ballot_sync(0xffffffffu, f | (lan >= OUTN));
    const bool all_f = out_phase && (m == 0xffffffffu);
    const float fac  = all_f ? DECAY : fac_long;   // decay^(S-1)

    if (lan < OUTN) {
        out[lan]        = f ? 1.0f : -1.0f;                   // out_t
        out[OUTN + lan] = out_phase ? ao * fac : 0.0f;        // pot_o
    }

    // Repair (not taken when all outputs fire at t=1): rescale speculative
    // pot_h from pot*DECAY to pot*fac_long.
    if (mt >= 1 && !all_f) {
        const float r = fac_long / DECAY;
        for (int i = lan; i < HID; i += 32)
            out[2 * OUTN + i] *= r;
    }
}

extern "C" void kernel_launch(void* const* d_in, const int* in_sizes, int n_in,
                              void* d_out, int out_size) {
    const float* spikes = (const float*)d_in[0];   // (40,)
    const float* w0     = (const float*)d_in[1];   // (40, 8192)
    const int*   tgt0   = (const int*)  d_in[2];   // (40, 8192)
    const float* w1     = (const float*)d_in[3];   // (16384, 11)
    const int*   tgt1   = (const int*)  d_in[4];   // (16384, 11)
    const int*   mt     = (const int*)  d_in[5];   // scalar max_timesteps
    float* out = (float*)d_out;

    snn_fused<<<NBLK, NTHR>>>(spikes, w0, tgt0, w1, tgt1, mt, out);
}

// round 11
// speedup vs baseline: 1.0226x; 1.0226x over previous
#include <cuda_runtime.h>

#define INN   40
#define HID   16384
#define OUTN  22
#define FAN0  8192
#define FAN1  11
#define THRESH 0.3f
#define NBLK  64
#define NTHR  256
#define NWARP (NTHR / 32)
#define NTOT  (NBLK * NTHR)             // 16384 threads == HID
#define ROWF  (NTHR * FAN1)             // floats in a block's w1 slice (2816)
#define V4N   (ROWF / 4)                // 704 float4 per array per block
#define DECAY 0.95122942450071400910f   // float32(exp(-1/20))

// Scratch — __device__ globals (allocation-free rule). g_add_h / g_add_o are
// zero at load and restored to zero every execution (zero-on-consume). g_bar is
// MONOTONIC (never reset): replay r uses window [2r*NBLK, 2(r+1)*NBLK); g_gen
// is the gate/replay counter on its OWN 128B line (R8: polls must not share a
// line with arrival atomics).
__device__ float g_add_h[HID];
__device__ float g_add_o[OUTN];
__device__ __align__(128) unsigned g_bar[32];   // [0]: monotonic arrival counter
__device__ __align__(128) unsigned g_gen[32];   // [0]: gate word / replay index

__device__ __forceinline__ unsigned ld_acquire_gpu(const unsigned* p) {
    unsigned v;
    asm volatile("ld.acquire.gpu.global.b32 %0, [%1];" : "=r"(v) : "l"(p) : "memory");
    return v;
}
__device__ __forceinline__ void st_release_gpu(unsigned* p, unsigned v) {
    asm volatile("st.release.gpu.global.b32 [%0], %1;" :: "l"(p), "r"(v) : "memory");
}

__global__ __launch_bounds__(NTHR, 1)
void snn_fused(const float* __restrict__ spikes,
               const float* __restrict__ w0,
               const int*   __restrict__ tgt0,
               const float* __restrict__ w1,
               const int*   __restrict__ tgt1,
               const int*   __restrict__ mt_p,
               float*       __restrict__ out)
{
    __shared__ float s_bins[NWARP][24];   // warp-private output bins (22 used)
    __shared__ float s_w1[ROWF];          // staged w1 slice (vec4)
    __shared__ int   s_t1[ROWF];          // staged tgt1 slice

    const int tid = threadIdx.x;
    const int gid = blockIdx.x * NTHR + tid;   // one hidden neuron per thread
    const int wrp = tid >> 5;
    const int lan = tid & 31;
    const int i0  = gid >> 11;                 // first input row of my chunks

    // ── Per-thread spike loads (warp-uniform addresses, 2 lines total).
    // No smem staging, no front __syncthreads: each warp starts phase B the
    // moment its own loads return.
    float spk[5];
#pragma unroll
    for (int k = 0; k < 5; ++k) spk[k] = __ldg(spikes + (i0 + 8 * k));

    // ── Vectorized speculative prefetch of phase-B operands (critical path).
    const float4* w0v = (const float4*)w0;
    const int4*   t0v = (const int4*)tgt0;
    float4 wv[5];
    int4   tv[5];
#pragma unroll
    for (int k = 0; k < 5; ++k) {
        wv[k] = __ldg(w0v + (gid + NTOT * k));
        tv[k] = __ldg(t0v + (gid + NTOT * k));
    }

    // ── Cooperative vec4 staging of this block's w1/tgt1 slice (contiguous).
    // STS before bar1's __syncthreads; consumed (cross-thread) after it.
    float4 swv[3];
    int4   stv[3];
    {
        const float4* wsrc = (const float4*)w1 + blockIdx.x * V4N;
        const int4*   tsrc = (const int4*)tgt1 + blockIdx.x * V4N;
#pragma unroll
        for (int i = 0; i < 3; ++i) {
            const int idx = tid + i * NTHR;
            if (idx < V4N) { swv[i] = __ldg(wsrc + idx); stv[i] = __ldg(tsrc + idx); }
        }
    }
    const int mt = __ldg(mt_p);
    const unsigned gen = *(volatile unsigned*)&g_gen[0];   // replay index

    // Warp-private bin zeroing — own row only, no block sync needed.
    if (lan < 24) s_bins[wrp][lan] = 0.0f;

    // fac_long = decay^(mt-1) (hidden under phase B; finisher/repair only)
    float fac_long = 1.0f;
    for (int k = 1; k < mt; ++k) fac_long *= DECAY;

    // ── Phase B: input -> hidden scatter (t=0). Per chunk: register spike
    // predicate (warp-uniform), 4 predicated REDs, operands in registers.
#pragma unroll
    for (int k = 0; k < 5; ++k) {
        const float s = 2.0f * spk[k];
        if (s != 0.0f) {
            atomicAdd(&g_add_h[tv[k].x], s * wv[k].x);
            atomicAdd(&g_add_h[tv[k].y], s * wv[k].y);
            atomicAdd(&g_add_h[tv[k].z], s * wv[k].z);
            atomicAdd(&g_add_h[tv[k].w], s * wv[k].w);
        }
    }

    // ── Park staged slices in shared (visibility via bar1's syncthreads).
    {
        float4* sw = (float4*)s_w1;
        int4*   st = (int4*)s_t1;
#pragma unroll
        for (int i = 0; i < 3; ++i) {
            const int idx = tid + i * NTHR;
            if (idx < V4N) { sw[idx] = swv[i]; st[idx] = stv[i]; }
        }
    }

    // ── Barrier 1: block arrival by tid0 (after syncthreads orders the
    // block's REDGs + STS), ALL threads acquire-poll the gate — no trailing
    // syncthreads, each warp resumes the moment it sees the release.
    __syncthreads();
    if (tid == 0) {
        __threadfence();                                       // release REDGs
        unsigned old = atomicAdd(&g_bar[0], 1u);
        if (old == (2u * gen + 1u) * NBLK - 1u)
            st_release_gpu(&g_gen[0], gen + 1u);               // open gate
    }
    while (ld_acquire_gpu(&g_gen[0]) == gen) { }               // per-thread

    // ── Phase C: hidden threshold (spikes possible only at t=0) + out scatter
    float a = g_add_h[gid] * DECAY;               // pot_h at end of t=0
    g_add_h[gid] = 0.0f;                          // zero-on-consume for replay
    const bool  sp  = (a >= THRESH);
    const float pot = sp ? 0.0f : a;

    // Speculative pot_h store: assume all_f=true => S=2 => fac=DECAY.
    out[2 * OUTN + gid] = (mt >= 1) ? pot * DECAY : 0.0f;

    if (sp) {
        const int base = tid * FAN1;
#pragma unroll
        for (int q = 0; q < FAN1; ++q)
            atomicAdd(&s_bins[wrp][s_t1[base + q]], s_w1[base + q]);
    }
    __syncthreads();                               // all warps' bins posted
    if (wrp != 0) return;                          // warps 1..7 done

    // ── Warp 0: post output partials, arrive; only the LAST block finalizes.
    float v = 0.0f;
    if (lan < OUTN) {
#pragma unroll
        for (int w = 0; w < NWARP; ++w) v += s_bins[w][lan];
        if (v != 0.0f) atomicAdd(&g_add_o[lan], v);
    }
    __threadfence();                               // block's adds + pot_h stores
    unsigned old = 0;
    if (lan == 0) old = atomicAdd(&g_bar[0], 1u);
    const bool fin = __shfl_sync(0xffffffffu, old, 0) == (2u * gen + 2u) * NBLK - 1u;
    if (!fin) return;                              // 63 blocks exit here

    // ── Finisher (warp 0 of last-arriving block): totals -> outputs (+repair)
    __threadfence();                               // acquire: all adds/stores
    float ao = 0.0f;
    if (lan < OUTN) {
        ao = g_add_o[lan];
        g_add_o[lan] = 0.0f;                       // zero-on-consume for replay
    }
    const bool out_phase = (mt >= 2);              // outputs fire at t=1 or never
    const bool f    = (lan < OUTN) && out_phase && (ao * DECAY >= THRESH);
    const unsigned m = __ballot_sync(0xffffffffu, f | (lan >= OUTN));
    const bool all_f = out_phase && (m == 0xffffffffu);
    const float fac  = all_f ? DECAY : fac_long;   // decay^(S-1)

    if (lan < OUTN) {
        out[lan]        = f ? 1.0f : -1.0f;                   // out_t
        out[OUTN + lan] = out_phase ? ao * fac : 0.0f;        // pot_o
    }

    // Repair (not taken when all outputs fire at t=1): rescale speculative
    // pot_h from pot*DECAY to pot*fac_long.
    if (mt >= 1 && !all_f) {
        const float r = fac_long / DECAY;
        for (int i = lan; i < HID; i += 32)
            out[2 * OUTN + i] *= r;
    }
}

extern "C" void kernel_launch(void* const* d_in, const int* in_sizes, int n_in,
                              void* d_out, int out_size) {
    const float* spikes = (const float*)d_in[0];   // (40,)
    const float* w0     = (const float*)d_in[1];   // (40, 8192)
    const int*   tgt0   = (const int*)  d_in[2];   // (40, 8192)
    const float* w1     = (const float*)d_in[3];   // (16384, 11)
    const int*   tgt1   = (const int*)  d_in[4];   // (16384, 11)
    const int*   mt     = (const int*)  d_in[5];   // scalar max_timesteps
    float* out = (float*)d_out;

    snn_fused<<<NBLK, NTHR>>>(spikes, w0, tgt0, w1, tgt1, mt, out);
}

// round 12
// speedup vs baseline: 1.0543x; 1.0310x over previous
#include <cuda_runtime.h>

#define INN   40
#define HID   16384
#define OUTN  22
#define FAN0  8192
#define FAN1  11
#define THRESH 0.3f
#define NBLK  64
#define NTHR  256
#define NWARP (NTHR / 32)
#define NTOT  (NBLK * NTHR)             // 16384 threads == HID
#define ROWF  (NTHR * FAN1)             // floats in a block's w1 slice (2816)
#define V4N   (ROWF / 4)                // 704 float4 per array per block
#define DECAY 0.95122942450071400910f   // float32(exp(-1/20))

// Scratch — __device__ globals (allocation-free rule). g_add_h / g_add_o are
// zero at load and restored to zero every execution (zero-on-consume). Sync
// words are MONOTONIC (never reset). g_sync[0] = arrival counter, g_sync[128]
// = gate/replay word: 512B apart => different L2 slices (bits>=8 differ), so
// spinner polls don't contend with arrival atomics at one LTS.
__device__ float g_add_h[HID];
__device__ float g_add_o[OUTN];
__device__ __align__(128) unsigned g_sync[256];   // [0]: bar ctr, [128]: gate

#define BAR_W (&g_sync[0])
#define GEN_W (&g_sync[128])

__device__ __forceinline__ unsigned ld_acquire_gpu(const unsigned* p) {
    unsigned v;
    asm volatile("ld.acquire.gpu.global.b32 %0, [%1];" : "=r"(v) : "l"(p) : "memory");
    return v;
}
__device__ __forceinline__ void st_release_gpu(unsigned* p, unsigned v) {
    asm volatile("st.release.gpu.global.b32 [%0], %1;" :: "l"(p), "r"(v) : "memory");
}
// Arrival atomic with acq_rel: releases this thread's (and, via the preceding
// bar.sync/__syncwarp, the block's) prior writes; acquires others' on return.
__device__ __forceinline__ unsigned atom_add_acqrel_gpu(unsigned* p, unsigned v) {
    unsigned old;
    asm volatile("atom.add.acq_rel.gpu.global.u32 %0, [%1], %2;"
                 : "=r"(old) : "l"(p), "r"(v) : "memory");
    return old;
}

__global__ __launch_bounds__(NTHR, 1)
void snn_fused(const float* __restrict__ spikes,
               const float* __restrict__ w0,
               const int*   __restrict__ tgt0,
               const float* __restrict__ w1,
               const int*   __restrict__ tgt1,
               const int*   __restrict__ mt_p,
               float*       __restrict__ out)
{
    __shared__ float s_bins[NWARP][24];   // warp-private output bins (22 used)
    __shared__ float s_w1[ROWF];          // staged w1 slice (vec4)
    __shared__ int   s_t1[ROWF];          // staged tgt1 slice

    const int tid = threadIdx.x;
    const int gid = blockIdx.x * NTHR + tid;   // one hidden neuron per thread
    const int wrp = tid >> 5;
    const int lan = tid & 31;
    const int i0  = gid >> 11;                 // first input row of my chunks

    // ── Per-thread spike loads (warp-uniform addresses, 2 lines total).
    float spk[5];
#pragma unroll
    for (int k = 0; k < 5; ++k) spk[k] = __ldg(spikes + (i0 + 8 * k));

    // ── Vectorized speculative prefetch of phase-B operands (critical path).
    const float4* w0v = (const float4*)w0;
    const int4*   t0v = (const int4*)tgt0;
    float4 wv[5];
    int4   tv[5];
#pragma unroll
    for (int k = 0; k < 5; ++k) {
        wv[k] = __ldg(w0v + (gid + NTOT * k));
        tv[k] = __ldg(t0v + (gid + NTOT * k));
    }

    // ── Cooperative vec4 staging of this block's w1/tgt1 slice (contiguous).
    float4 swv[3];
    int4   stv[3];
    {
        const float4* wsrc = (const float4*)w1 + blockIdx.x * V4N;
        const int4*   tsrc = (const int4*)tgt1 + blockIdx.x * V4N;
#pragma unroll
        for (int i = 0; i < 3; ++i) {
            const int idx = tid + i * NTHR;
            if (idx < V4N) { swv[i] = __ldg(wsrc + idx); stv[i] = __ldg(tsrc + idx); }
        }
    }
    const int mt = __ldg(mt_p);
    const unsigned gen = ld_acquire_gpu(GEN_W);   // replay index

    // Warp-private bin zeroing — own row only, no block sync needed.
    if (lan < 24) s_bins[wrp][lan] = 0.0f;

    // fac_long = decay^(mt-1) (hidden under phase B; finisher/repair only)
    float fac_long = 1.0f;
    for (int k = 1; k < mt; ++k) fac_long *= DECAY;

    // ── Phase B: input -> hidden scatter (t=0). Register spike predicate
    // (warp-uniform), 4 predicated REDs per chunk, operands in registers.
#pragma unroll
    for (int k = 0; k < 5; ++k) {
        const float s = 2.0f * spk[k];
        if (s != 0.0f) {
            atomicAdd(&g_add_h[tv[k].x], s * wv[k].x);
            atomicAdd(&g_add_h[tv[k].y], s * wv[k].y);
            atomicAdd(&g_add_h[tv[k].z], s * wv[k].z);
            atomicAdd(&g_add_h[tv[k].w], s * wv[k].w);
        }
    }

    // ── Park staged slices in shared (visibility via bar1's syncthreads).
    {
        float4* sw = (float4*)s_w1;
        int4*   st = (int4*)s_t1;
#pragma unroll
        for (int i = 0; i < 3; ++i) {
            const int idx = tid + i * NTHR;
            if (idx < V4N) { sw[idx] = swv[i]; st[idx] = stv[i]; }
        }
    }

    // ── Barrier 1: bar.sync orders the block's REDGs+STS before tid0's
    // acq_rel arrival (no MEMBAR needed); all threads acquire-poll the gate.
    __syncthreads();
    if (tid == 0) {
        unsigned old = atom_add_acqrel_gpu(BAR_W, 1u);
        if (old == (2u * gen + 1u) * NBLK - 1u)
            st_release_gpu(GEN_W, gen + 1u);               // open gate
    }
    while (ld_acquire_gpu(GEN_W) == gen) { }               // per-thread resume

    // ── Phase C: hidden threshold (spikes possible only at t=0) + out scatter
    float a = g_add_h[gid] * DECAY;               // pot_h at end of t=0
    g_add_h[gid] = 0.0f;                          // zero-on-consume for replay
    const bool  sp  = (a >= THRESH);
    const float pot = sp ? 0.0f : a;

    // Speculative pot_h store: assume all_f=true => S=2 => fac=DECAY.
    out[2 * OUTN + gid] = (mt >= 1) ? pot * DECAY : 0.0f;

    if (sp) {
        const int base = tid * FAN1;
#pragma unroll
        for (int q = 0; q < FAN1; ++q)
            atomicAdd(&s_bins[wrp][s_t1[base + q]], s_w1[base + q]);
    }
    __syncthreads();                               // all warps' bins + pot_h stores
    if (wrp != 0) return;                          // warps 1..7 done

    // ── Warp 0: post output partials; acq_rel arrival (after __syncwarp)
    // releases the block's adds + pot_h stores. Only the LAST block finalizes.
    float v = 0.0f;
    if (lan < OUTN) {
#pragma unroll
        for (int w = 0; w < NWARP; ++w) v += s_bins[w][lan];
        if (v != 0.0f) atomicAdd(&g_add_o[lan], v);
    }
    __syncwarp();                                  // order lanes' REDGs pre-arrival
    unsigned old = 0;
    if (lan == 0) old = atom_add_acqrel_gpu(BAR_W, 1u);
    const bool fin = __shfl_sync(0xffffffffu, old, 0) == (2u * gen + 2u) * NBLK - 1u;
    if (!fin) return;                              // 63 blocks exit here

    // ── Finisher (warp 0 of last block): acquire came from its arrival.
    float ao = 0.0f;
    if (lan < OUTN) {
        ao = g_add_o[lan];
        g_add_o[lan] = 0.0f;                       // zero-on-consume for replay
    }
    const bool out_phase = (mt >= 2);              // outputs fire at t=1 or never
    const bool f    = (lan < OUTN) && out_phase && (ao * DECAY >= THRESH);
    const unsigned m = __ballot_sync(0xffffffffu, f | (lan >= OUTN));
    const bool all_f = out_phase && (m == 0xffffffffu);
    const float fac  = all_f ? DECAY : fac_long;   // decay^(S-1)

    if (lan < OUTN) {
        out[lan]        = f ? 1.0f : -1.0f;                   // out_t
        out[OUTN + lan] = out_phase ? ao * fac : 0.0f;        // pot_o
    }

    // Repair (not taken when all outputs fire at t=1): rescale speculative
    // pot_h from pot*DECAY to pot*fac_long. All blocks' pot_h stores are
    // visible via the acq_rel arrival chain.
    if (mt >= 1 && !all_f) {
        const float r = fac_long / DECAY;
        for (int i = lan; i < HID; i += 32)
            out[2 * OUTN + i] *= r;
    }
}

extern "C" void kernel_launch(void* const* d_in, const int* in_sizes, int n_in,
                              void* d_out, int out_size) {
    const float* spikes = (const float*)d_in[0];   // (40,)
    const float* w0     = (const float*)d_in[1];   // (40, 8192)
    const int*   tgt0   = (const int*)  d_in[2];   // (40, 8192)
    const float* w1     = (const float*)d_in[3];   // (16384, 11)
    const int*   tgt1   = (const int*)  d_in[4];   // (16384, 11)
    const int*   mt     = (const int*)  d_in[5];   // scalar max_timesteps
    float* out = (float*)d_out;

    snn_fused<<<NBLK, NTHR>>>(spikes, w0, tgt0, w1, tgt1, mt, out);
}